// round 6
// baseline (speedup 1.0000x reference)
#include <cuda_runtime.h>
#include <cstdint>

// Fixed problem shapes
#define ND   256    // node_dim
#define CD   512    // cond_dim
#define OD   128    // out_dim
#define HID  64     // hidden
#define NB   64     // batch (graphs)
#define NMAX 100000

// -------- device scratch (no allocations allowed) --------
__device__ __align__(16) float g_x[NMAX * OD];    // node feats after lin layer
__device__ __align__(16) float g_agg[NMAX * OD];  // edge aggregation accumulator
__device__ __align__(16) float g_wn[HID * OD];    // normalized lin weights, k-major
__device__ float g_gamma[NB * HID];
__device__ float g_beta[NB * HID];
__device__ float g_cnt[NMAX];
__device__ const float* d_gainp[2];   // [0]=cond_w_g, [1]=lin_w_g
__device__ const float* d_biasp[2];   // [0]=cond_b,   [1]=lin_b
__device__ int d_ei64;                // 1 if edge_index is int64
__device__ int d_n2g64;               // 1 if node2graph is int64

// ============================================================
// Kernel C: classify the four 128-vectors + index dtypes
// ============================================================
__global__ void k_classify(const float* q0, const float* q1,
                           const float* q2, const float* q3,
                           const int* ei32, const int* n2g32, int N)
{
    if (threadIdx.x != 0 || blockIdx.x != 0) return;
    const float* qs[4] = {q0, q1, q2, q3};
    int gi = 0, bi = 0;
    #pragma unroll
    for (int j = 0; j < 4; j++) {
        int small = 0;
        for (int k = 0; k < 128; k++) small += (qs[j][k] < 0.3f) ? 1 : 0;
        if (small > 64) { if (bi < 2) d_biasp[bi++] = qs[j]; }
        else            { if (gi < 2) d_gainp[gi++] = qs[j]; }
    }
    if (gi < 2) { d_gainp[0] = q0; d_gainp[1] = q2; }
    if (bi < 2) { d_biasp[0] = q1; d_biasp[1] = q3; }

    // edge_index dtype: odd int32 slots at head are high-words (0) iff int64
    int orv = 0;
    for (int k = 0; k < 64; k++) orv |= ei32[2 * k + 1];
    d_ei64 = (orv == 0) ? 1 : 0;

    // node2graph dtype: odd int32 slots near tail (sorted ids ~63 if int32)
    int st = (N - 2) | 1;
    int orn = 0;
    for (int k = 0; k < 32; k++) orn |= n2g32[st - 2 * k];
    d_n2g64 = (orn == 0) ? 1 : 0;
}

// ============================================================
// Kernel 0: zero g_agg and g_cnt (graph-replay safe)
// ============================================================
__global__ void k_zero(int total4, int nNodes) {
    int i = blockIdx.x * blockDim.x + threadIdx.x;
    if (i < total4) ((float4*)g_agg)[i] = make_float4(0.f, 0.f, 0.f, 0.f);
    if (i < nNodes) g_cnt[i] = 0.f;
}

// ============================================================
// Kernel 0b: weight-norm lin weights -> g_wn (k-major [64][128])
// ============================================================
__global__ void k_wnorm(const float* __restrict__ wv)  // [128, 64]
{
    int o = threadIdx.x;
    const float* wg = d_gainp[1];
    const float* wr = wv + o * HID;
    float s2 = 0.f;
    #pragma unroll 8
    for (int k = 0; k < HID; k++) { float v = wr[k]; s2 += v * v; }
    float scale = wg[o] * rsqrtf(s2);
    #pragma unroll 8
    for (int k = 0; k < HID; k++) g_wn[k * OD + o] = wr[k] * scale;
}

// ============================================================
// Kernel 1: cond projection -> gamma/beta. grid=OD, 128 thr
// ============================================================
__global__ void k_cond(const float* __restrict__ cf,   // [NB, CD]
                       const float* __restrict__ wv)   // [OD, CD]
{
    int o = blockIdx.x;
    int t = threadIdx.x;
    __shared__ float red[4];
    const float* wg = d_gainp[0];
    const float* cb = d_biasp[0];

    float s2 = 0.f;
    for (int k = t; k < CD; k += 128) { float v = wv[o * CD + k]; s2 += v * v; }
    #pragma unroll
    for (int d = 16; d; d >>= 1) s2 += __shfl_xor_sync(0xFFFFFFFFu, s2, d);
    if ((t & 31) == 0) red[t >> 5] = s2;
    __syncthreads();
    float norm2 = red[0] + red[1] + red[2] + red[3];
    float scale = wg[o] * rsqrtf(norm2);

    if (t < NB) {
        float acc = 0.f;
        const float* cfr = cf + t * CD;
        const float* wr = wv + o * CD;
        #pragma unroll 8
        for (int k = 0; k < CD; k++) acc += cfr[k] * wr[k];
        float val = acc * scale + cb[o];
        if (o < HID) g_gamma[t * HID + o] = val + 1.0f;
        else         g_beta[t * HID + (o - HID)] = val;
    }
}

// ============================================================
// Kernel 2: fused node transform (33.8KB static smem)
// ============================================================
__global__ void __launch_bounds__(256) k_node(
    const float* __restrict__ feats,     // [N, 256]
    const float* __restrict__ film_w,    // [64, 256]
    const float* __restrict__ film_b,    // [64]
    const void*  __restrict__ n2g,       // [N] int32 or int64
    int nNodes)
{
    __shared__ __align__(16) float sAt[32 * 68];
    __shared__ __align__(16) float sWt[32 * 68];
    __shared__ __align__(16) float sH[64 * 64];

    const int t = threadIdx.x;
    const int node0 = blockIdx.x * 64;

    // ---- GEMM 1: [64 x 256] @ [256 x 64]^T, k chunks of 32 ----
    const int tx = t & 15, ty = t >> 4;
    float acc[4][4];
    #pragma unroll
    for (int r = 0; r < 4; r++)
        #pragma unroll
        for (int c = 0; c < 4; c++) acc[r][c] = 0.f;

    for (int k0 = 0; k0 < ND; k0 += 32) {
        __syncthreads();
        for (int q = t; q < 512; q += 256) {
            int row = q >> 3;
            int c4  = q & 7;
            int gk  = k0 + c4 * 4;
            float4 va = (node0 + row < nNodes)
                ? *(const float4*)(feats + (size_t)(node0 + row) * ND + gk)
                : make_float4(0.f, 0.f, 0.f, 0.f);
            sAt[(c4 * 4 + 0) * 68 + row] = va.x;
            sAt[(c4 * 4 + 1) * 68 + row] = va.y;
            sAt[(c4 * 4 + 2) * 68 + row] = va.z;
            sAt[(c4 * 4 + 3) * 68 + row] = va.w;
            float4 vw = *(const float4*)(film_w + row * ND + gk);
            sWt[(c4 * 4 + 0) * 68 + row] = vw.x;
            sWt[(c4 * 4 + 1) * 68 + row] = vw.y;
            sWt[(c4 * 4 + 2) * 68 + row] = vw.z;
            sWt[(c4 * 4 + 3) * 68 + row] = vw.w;
        }
        __syncthreads();
        #pragma unroll
        for (int kk = 0; kk < 32; kk++) {
            float4 a = *(const float4*)&sAt[kk * 68 + ty * 4];
            float4 w = *(const float4*)&sWt[kk * 68 + tx * 4];
            acc[0][0] += a.x * w.x; acc[0][1] += a.x * w.y; acc[0][2] += a.x * w.z; acc[0][3] += a.x * w.w;
            acc[1][0] += a.y * w.x; acc[1][1] += a.y * w.y; acc[1][2] += a.y * w.z; acc[1][3] += a.y * w.w;
            acc[2][0] += a.z * w.x; acc[2][1] += a.z * w.y; acc[2][2] += a.z * w.z; acc[2][3] += a.z * w.w;
            acc[3][0] += a.w * w.x; acc[3][1] += a.w * w.y; acc[3][2] += a.w * w.z; acc[3][3] += a.w * w.w;
        }
    }
    __syncthreads();

    #pragma unroll
    for (int r = 0; r < 4; r++)
        #pragma unroll
        for (int c = 0; c < 4; c++)
            sH[(ty * 4 + r) * 64 + tx * 4 + c] = acc[r][c] + __ldg(&film_b[tx * 4 + c]);
    __syncthreads();

    // ---- LayerNorm + FiLM + relu ----
    {
        const int w = t >> 5, lane = t & 31;
        const int is64 = d_n2g64;
        #pragma unroll
        for (int r = 0; r < 8; r++) {
            int i = w * 8 + r;
            int node = node0 + i;
            float v0 = sH[i * 64 + lane];
            float v1 = sH[i * 64 + 32 + lane];
            float s = v0 + v1;
            #pragma unroll
            for (int d = 16; d; d >>= 1) s += __shfl_xor_sync(0xFFFFFFFFu, s, d);
            float mu = s * (1.0f / 64.0f);
            float d0 = v0 - mu, d1 = v1 - mu;
            float q = d0 * d0 + d1 * d1;
            #pragma unroll
            for (int d = 16; d; d >>= 1) q += __shfl_xor_sync(0xFFFFFFFFu, q, d);
            float rstd = rsqrtf(q * (1.0f / 64.0f) + 1e-5f);
            int idx = (node < nNodes) ? node : 0;
            int g = is64 ? (int)((const long long*)n2g)[idx]
                         : ((const int*)n2g)[idx];
            g &= (NB - 1);
            const float* gp = g_gamma + g * HID;
            const float* bp = g_beta + g * HID;
            float y0 = fmaxf(gp[lane]      * (d0 * rstd) + bp[lane],      0.f);
            float y1 = fmaxf(gp[lane + 32] * (d1 * rstd) + bp[lane + 32], 0.f);
            sH[i * 64 + lane]      = y0;
            sH[i * 64 + 32 + lane] = y1;
        }
    }
    __syncthreads();

    // ---- GEMM 2: [64 x 64] @ [64 x 128] -> g_x ----
    {
        const int tx2 = t & 31, ty2 = t >> 5;
        float acc2[8][4];
        #pragma unroll
        for (int r = 0; r < 8; r++)
            #pragma unroll
            for (int c = 0; c < 4; c++) acc2[r][c] = 0.f;

        #pragma unroll 4
        for (int k = 0; k < HID; k++) {
            float4 wv = __ldg((const float4*)&g_wn[k * OD + tx2 * 4]);
            #pragma unroll
            for (int r = 0; r < 8; r++) {
                float a = sH[(ty2 * 8 + r) * 64 + k];
                acc2[r][0] += a * wv.x;
                acc2[r][1] += a * wv.y;
                acc2[r][2] += a * wv.z;
                acc2[r][3] += a * wv.w;
            }
        }
        const float* lb = d_biasp[1];
        float bx = lb[tx2 * 4 + 0], by = lb[tx2 * 4 + 1];
        float bz = lb[tx2 * 4 + 2], bw = lb[tx2 * 4 + 3];
        #pragma unroll
        for (int r = 0; r < 8; r++) {
            int node = node0 + ty2 * 8 + r;
            if (node < nNodes) {
                float4 o;
                o.x = acc2[r][0] + bx;
                o.y = acc2[r][1] + by;
                o.z = acc2[r][2] + bz;
                o.w = acc2[r][3] + bw;
                *(float4*)(g_x + (size_t)node * OD + tx2 * 4) = o;
            }
        }
    }
}

// ============================================================
// Kernel 3: edge scatter-add (one warp per edge, scalar atomics)
// ============================================================
__global__ void k_edge(const void* __restrict__ eiv,  // [2,E] int32 or int64
                       int E, int nNodes)
{
    long long gid = (long long)blockIdx.x * blockDim.x + threadIdx.x;
    int e = (int)(gid >> 5);
    if (e >= E) return;
    int lane = threadIdx.x & 31;
    int src, dst;
    if (d_ei64) {
        const long long* ei = (const long long*)eiv;
        src = (int)ei[e];
        dst = (int)ei[(size_t)E + e];
    } else {
        const int* ei = (const int*)eiv;
        src = ei[e];
        dst = ei[(size_t)E + e];
    }
    if ((unsigned)src >= (unsigned)nNodes || (unsigned)dst >= (unsigned)nNodes) return;
    float4 v = ((const float4*)g_x)[(size_t)src * 32 + lane];
    float* p = g_agg + (size_t)dst * OD + lane * 4;
    atomicAdd(p + 0, v.x);
    atomicAdd(p + 1, v.y);
    atomicAdd(p + 2, v.z);
    atomicAdd(p + 3, v.w);
    if (lane == 0) atomicAdd(&g_cnt[dst], 1.0f);
}

// ============================================================
// Kernel 4: finalize — mean + relu, plain store to d_out
// ============================================================
__global__ void k_final(float4* __restrict__ out4, int nNodes) {
    int i = blockIdx.x * blockDim.x + threadIdx.x;
    int total4 = nNodes * 32;
    if (i >= total4) return;
    int row = i >> 5;
    float c = g_cnt[row];
    float s = 1.0f / fmaxf(c, 1.0f);
    float4 v = ((const float4*)g_agg)[i];
    v.x = fmaxf(v.x * s, 0.f);
    v.y = fmaxf(v.y * s, 0.f);
    v.z = fmaxf(v.z * s, 0.f);
    v.w = fmaxf(v.w * s, 0.f);
    out4[i] = v;
}

// ============================================================
extern "C" void kernel_launch(void* const* d_in, const int* in_sizes, int n_in,
                              void* d_out, int out_size)
{
    // ---- order-free identification by element count ----
    const float *node_feats = 0, *cond_feats = 0, *cond_w_v = 0;
    const float *film_w = 0, *film_b = 0, *lin_w_v = 0;
    const void  *edge_index = 0, *node2graph = 0;
    const float *quad[4] = {0, 0, 0, 0};
    int nq = 0;
    int nNodes = NMAX, E = 1600000;

    for (int i = 0; i < n_in; i++) {
        int s = in_sizes[i];
        const void* p = d_in[i];
        switch (s) {
            case NMAX * ND:   node_feats = (const float*)p; nNodes = s / ND; break;
            case 2 * 1600000: edge_index = p; E = s / 2; break;
            case OD * CD:     cond_w_v   = (const float*)p; break;
            case NB * CD:     cond_feats = (const float*)p; break;
            case HID * ND:    film_w     = (const float*)p; break;
            case OD * HID:    lin_w_v    = (const float*)p; break;
            case NMAX:        node2graph = p; break;
            case HID:         film_b     = (const float*)p; break;
            case OD:          if (nq < 4) quad[nq++] = (const float*)p; break;
            default: break;
        }
    }
    if (!node_feats || !edge_index || !node2graph || nq < 4) return;

    float* out = (float*)d_out;

    k_classify<<<1, 32>>>(quad[0], quad[1], quad[2], quad[3],
                          (const int*)edge_index, (const int*)node2graph, nNodes);
    {
        int total4 = nNodes * 32;
        int blocks = (total4 + 255) / 256;
        k_zero<<<blocks, 256>>>(total4, nNodes);
    }
    k_wnorm<<<1, 128>>>(lin_w_v);
    k_cond<<<OD, 128>>>(cond_feats, cond_w_v);
    {
        int blocks = (nNodes + 63) / 64;
        k_node<<<blocks, 256>>>(node_feats, film_w, film_b, node2graph, nNodes);
    }
    {
        long long work = (long long)E * 32;
        int blocks = (int)((work + 255) / 256);
        k_edge<<<blocks, 256>>>(edge_index, E, nNodes);
    }
    {
        int total4 = nNodes * 32;
        int blocks = (total4 + 255) / 256;
        k_final<<<blocks, 256>>>((float4*)out, nNodes);
    }
}